// round 8
// baseline (speedup 1.0000x reference)
#include <cuda_runtime.h>
#include <math_constants.h>

#define NB   32
#define LT   2048
#define CC   128
#define J    128         // chunks along L
#define TC   (LT / J)    // 16 rows per chunk
#define WPB  8           // warps per block (one chunk per warp)
#define OUTW 1172        // 3*384 + 20
#define NLC  ((size_t)NB * LT * CC)          // 8,388,608
#define OUT_ELEMS ((size_t)NB * LT * OUTW)   // 76,808,192

// chunk aggregates -> (after scan_kernel) exclusive prefixes: [3][32][J][128]
__device__ float g_cmax[3 * NB * J * CC];
__device__ int   g_carg[3 * NB * J * CC];
__device__ float g_csum[3 * NB * J * CC];

// ---------------- pass A: per-chunk aggregates (warp per chunk, float4/lane) --
__global__ void __launch_bounds__(32 * WPB) agg_kernel(const float* __restrict__ x0,
                                                       const float* __restrict__ x1,
                                                       const float* __restrict__ x2) {
    const int w = threadIdx.x >> 5;
    const int l = threadIdx.x & 31;
    const int j = blockIdx.x * WPB + w;
    const int n = blockIdx.y, i = blockIdx.z;
    const float* x = (i == 0) ? x0 : (i == 1) ? x1 : x2;
    const float4* p = (const float4*)(x + ((size_t)n * LT + (size_t)j * TC) * CC) + l;

    float m0 = -CUDART_INF_F, m1 = m0, m2 = m0, m3 = m0;
    float s0 = 0.f, s1 = 0.f, s2 = 0.f, s3 = 0.f;
    int a0 = 0, a1 = 0, a2 = 0, a3 = 0;
#pragma unroll
    for (int t = 0; t < TC; ++t) {
        float4 v = p[t * 32];
        const int T = j * TC + t;
        s0 += v.x; s1 += v.y; s2 += v.z; s3 += v.w;
        if (v.x > m0) { m0 = v.x; a0 = T; }
        if (v.y > m1) { m1 = v.y; a1 = T; }
        if (v.z > m2) { m2 = v.z; a2 = T; }
        if (v.w > m3) { m3 = v.w; a3 = T; }
    }
    const int idx = ((i * NB + n) * J + j) * CC + 4 * l;
    *(float4*)&g_cmax[idx] = make_float4(m0, m1, m2, m3);
    *(int4*)  &g_carg[idx] = make_int4(a0, a1, a2, a3);
    *(float4*)&g_csum[idx] = make_float4(s0, s1, s2, s3);
}

// ---------------- pass A2: in-place exclusive scan of aggregates along J ------
// one thread per (i, n, c) lane; data is L2-resident (19 MB)
__global__ void __launch_bounds__(256) scan_kernel() {
    const int tid = blockIdx.x * 256 + threadIdx.x;   // 0 .. 3*NB*CC-1
    const int c = tid % CC;
    const int in = tid / CC;                          // i*NB + n
    const int base = in * (J * CC) + c;

    float pm = -CUDART_INF_F, ps = 0.f;
    int pa = 0;
#pragma unroll 4
    for (int j = 0; j < J; ++j) {
        const int idx = base + j * CC;
        float m = g_cmax[idx];
        int   a = g_carg[idx];
        float s = g_csum[idx];
        g_cmax[idx] = pm;
        g_carg[idx] = pa;
        g_csum[idx] = ps;
        if (m > pm) { pm = m; pa = a; }
        ps += s;
    }
}

// ---------------- pass B: load prefix, emit all outputs -----------------------
__global__ void __launch_bounds__(32 * WPB) emit_kernel(const float* __restrict__ x0,
                                                        const float* __restrict__ x1,
                                                        const float* __restrict__ x2,
                                                        const float* __restrict__ dem,
                                                        const float* __restrict__ W1,
                                                        const float* __restrict__ b1,
                                                        const float* __restrict__ W2,
                                                        const float* __restrict__ b2,
                                                        float* __restrict__ out) {
    const int w = threadIdx.x >> 5;
    const int l = threadIdx.x & 31;
    const int j = blockIdx.x * WPB + w;
    const int n = blockIdx.y, i = blockIdx.z;
    const float* x = (i == 0) ? x0 : (i == 1) ? x1 : x2;

    // -- demographic MLP (only needed by i==0 blocks; recomputed per block) ----
    __shared__ float h_sh[40];
    __shared__ float d_sh[20];
    if (i == 0 && threadIdx.x < 40) {
        const int o = threadIdx.x;
        float s = b1[o];
#pragma unroll
        for (int k = 0; k < 8; ++k) s = fmaf(dem[n * 8 + k], W1[k * 40 + o], s);
        h_sh[o] = fmaxf(s, 0.f);
    }
    __syncthreads();
    if (i == 0 && threadIdx.x < 20) {
        const int o = threadIdx.x;
        float s = b2[o];
#pragma unroll
        for (int k = 0; k < 40; ++k) s = fmaf(h_sh[k], W2[k * 20 + o], s);
        d_sh[o] = fmaxf(s, 0.f);
    }
    __syncthreads();

    // -- exclusive prefix for this chunk: one vector load (precomputed) --------
    const int pidx = ((i * NB + n) * J + j) * CC + 4 * l;
    float4 m4 = *(const float4*)&g_cmax[pidx];
    int4   a4 = *(const int4*)  &g_carg[pidx];
    float4 s4 = *(const float4*)&g_csum[pidx];
    float pm0 = m4.x, pm1 = m4.y, pm2 = m4.z, pm3 = m4.w;
    int   pa0 = a4.x, pa1 = a4.y, pa2 = a4.z, pa3 = a4.w;
    float ps0 = s4.x, ps1 = s4.y, ps2 = s4.z, ps3 = s4.w;

    const size_t row0 = (size_t)n * LT + (size_t)j * TC;
    const float4* p = (const float4*)(x + row0 * CC) + l;

    float* obase = out + row0 * OUTW + (size_t)i * 384 + 4 * l;
    float* ibase = out + OUT_ELEMS + (size_t)i * NLC + row0 * CC + 4 * l;
    float* abase = ibase + 3 * NLC;

    const float inv_L = 1.0f / (float)LT;

#pragma unroll 4
    for (int t = 0; t < TC; ++t) {
        const int T = j * TC + t;
        float4 v = p[t * 32];
        ps0 += v.x; ps1 += v.y; ps2 += v.z; ps3 += v.w;
        if (v.x > pm0) { pm0 = v.x; pa0 = T; }
        if (v.y > pm1) { pm1 = v.y; pa1 = T; }
        if (v.z > pm2) { pm2 = v.z; pa2 = T; }
        if (v.w > pm3) { pm3 = v.w; pa3 = T; }

        const bool pad = (T < LT - 1);        // window still contains left-pad zeros
        const float padi = (float)(T - (LT - 1));
        float4 pmax = make_float4(pad ? fmaxf(pm0, 0.f) : pm0,
                                  pad ? fmaxf(pm1, 0.f) : pm1,
                                  pad ? fmaxf(pm2, 0.f) : pm2,
                                  pad ? fmaxf(pm3, 0.f) : pm3);
        float4 ind = make_float4((pad && pm0 < 0.f) ? padi : (float)pa0,
                                 (pad && pm1 < 0.f) ? padi : (float)pa1,
                                 (pad && pm2 < 0.f) ? padi : (float)pa2,
                                 (pad && pm3 < 0.f) ? padi : (float)pa3);
        float4 pavg = make_float4(ps0 * inv_L, ps1 * inv_L, ps2 * inv_L, ps3 * inv_L);
        const float rc = __frcp_rn((float)(T + 1));
        float4 psum = make_float4(ps0 * rc, ps1 * rc, ps2 * rc, ps3 * rc);

        float* orow = obase + (size_t)t * OUTW;
        __stcs((float4*)(orow),        pmax);
        __stcs((float4*)(orow + 128),  pavg);
        __stcs((float4*)(orow + 256),  psum);
        __stcs((float4*)(ibase + t * CC), ind);
        __stcs((float4*)(abase + t * CC), pmax);
    }

    // -- demographic broadcast cols [1152:1172), written once (i==0 blocks) ---
    if (i == 0) {
        float4 dv[5];
#pragma unroll
        for (int g = 0; g < 5; ++g)
            dv[g] = *(const float4*)&d_sh[4 * g];
#pragma unroll
        for (int q = l; q < TC * 5; q += 32) {
            const int t = q / 5, g = q % 5;
            __stcs((float4*)(out + (row0 + t) * OUTW + 1152 + 4 * g), dv[g]);
        }
    }
}

extern "C" void kernel_launch(void* const* d_in, const int* in_sizes, int n_in,
                              void* d_out, int out_size) {
    const float* inp0 = (const float*)d_in[0];
    const float* inp1 = (const float*)d_in[1];
    const float* inp2 = (const float*)d_in[2];
    const float* dem  = (const float*)d_in[3];
    const float* W1   = (const float*)d_in[4];
    const float* b1   = (const float*)d_in[5];
    const float* W2   = (const float*)d_in[6];
    const float* b2   = (const float*)d_in[7];
    float* out = (float*)d_out;

    dim3 grid(J / WPB, NB, 3);   // 16 x 32 x 3 = 1536 blocks, warp per chunk
    agg_kernel<<<grid, 32 * WPB>>>(inp0, inp1, inp2);
    scan_kernel<<<(3 * NB * CC) / 256, 256>>>();
    emit_kernel<<<grid, 32 * WPB>>>(inp0, inp1, inp2, dem, W1, b1, W2, b2, out);
}

// round 12
// speedup vs baseline: 1.3322x; 1.3322x over previous
#include <cuda_runtime.h>
#include <math_constants.h>

#define NB   32
#define LT   2048
#define CC   128
#define J    64          // chunks along L
#define TC   (LT / J)    // 32 rows per chunk
#define OUTW 1172        // 3*384 + 20
#define NLC  ((size_t)NB * LT * CC)          // 8,388,608
#define OUT_ELEMS ((size_t)NB * LT * OUTW)   // 76,808,192

// chunk aggregates: [3][32][J][128] (c contiguous)
__device__ float g_cmax[3 * NB * J * CC];
__device__ int   g_carg[3 * NB * J * CC];
__device__ float g_csum[3 * NB * J * CC];

// ---------------- pass A: per-chunk aggregates (warp per chunk, float4/lane) --
__global__ void __launch_bounds__(256) agg_kernel(const float* __restrict__ x0,
                                                  const float* __restrict__ x1,
                                                  const float* __restrict__ x2) {
    const int w = threadIdx.x >> 5;
    const int l = threadIdx.x & 31;
    const int j = blockIdx.x * 8 + w;
    const int n = blockIdx.y, i = blockIdx.z;
    const float* x = (i == 0) ? x0 : (i == 1) ? x1 : x2;
    const float4* p = (const float4*)(x + ((size_t)n * LT + (size_t)j * TC) * CC) + l;

    float m0 = -CUDART_INF_F, m1 = m0, m2 = m0, m3 = m0;
    float s0 = 0.f, s1 = 0.f, s2 = 0.f, s3 = 0.f;
    int a0 = 0, a1 = 0, a2 = 0, a3 = 0;
#pragma unroll 8
    for (int t = 0; t < TC; ++t) {
        float4 v = p[t * 32];
        const int T = j * TC + t;
        s0 += v.x; s1 += v.y; s2 += v.z; s3 += v.w;
        if (v.x > m0) { m0 = v.x; a0 = T; }
        if (v.y > m1) { m1 = v.y; a1 = T; }
        if (v.z > m2) { m2 = v.z; a2 = T; }
        if (v.w > m3) { m3 = v.w; a3 = T; }
    }
    const int idx = ((i * NB + n) * J + j) * CC + 4 * l;
    *(float4*)&g_cmax[idx] = make_float4(m0, m1, m2, m3);
    *(int4*)  &g_carg[idx] = make_int4(a0, a1, a2, a3);
    *(float4*)&g_csum[idx] = make_float4(s0, s1, s2, s3);
}

// ---------------- pass B: 2 warps per chunk (float2/lane), fold + emit --------
__global__ void __launch_bounds__(256, 6) emit_kernel(const float* __restrict__ x0,
                                                      const float* __restrict__ x1,
                                                      const float* __restrict__ x2,
                                                      const float* __restrict__ dem,
                                                      const float* __restrict__ W1,
                                                      const float* __restrict__ b1,
                                                      const float* __restrict__ W2,
                                                      const float* __restrict__ b2,
                                                      float* __restrict__ out) {
    const int w = threadIdx.x >> 5;          // 8 warps: 4 chunks x 2 halves
    const int l = threadIdx.x & 31;
    const int half = w & 1;                  // channel half: [0:64) or [64:128)
    const int j = blockIdx.x * 4 + (w >> 1); // chunk
    const int n = blockIdx.y, i = blockIdx.z;
    const float* x = (i == 0) ? x0 : (i == 1) ? x1 : x2;
    const int c0 = half * 64 + 2 * l;        // this lane's 2 channels

    // -- demographic MLP (recomputed per block; used by i==0 blocks) ----------
    __shared__ float h_sh[40];
    __shared__ float d_sh[20];
    if (i == 0 && threadIdx.x < 40) {
        const int o = threadIdx.x;
        float s = b1[o];
#pragma unroll
        for (int k = 0; k < 8; ++k) s = fmaf(dem[n * 8 + k], W1[k * 40 + o], s);
        h_sh[o] = fmaxf(s, 0.f);
    }
    __syncthreads();
    if (i == 0 && threadIdx.x < 20) {
        const int o = threadIdx.x;
        float s = b2[o];
#pragma unroll
        for (int k = 0; k < 40; ++k) s = fmaf(h_sh[k], W2[k * 20 + o], s);
        d_sh[o] = fmaxf(s, 0.f);
    }
    __syncthreads();

    // -- exclusive prefix over earlier chunks (L2-resident aggregates) --------
    float pm0 = -CUDART_INF_F, pm1 = pm0;
    float ps0 = 0.f, ps1 = 0.f;
    int pa0 = 0, pa1 = 0;
    const int base = ((i * NB + n) * J) * CC + c0;
#pragma unroll 4
    for (int k = 0; k < j; ++k) {
        float2 m = *(const float2*)&g_cmax[base + k * CC];
        int2   a = *(const int2*)  &g_carg[base + k * CC];
        float2 s = *(const float2*)&g_csum[base + k * CC];
        if (m.x > pm0) { pm0 = m.x; pa0 = a.x; }
        if (m.y > pm1) { pm1 = m.y; pa1 = a.y; }
        ps0 += s.x; ps1 += s.y;
    }

    const size_t row0 = (size_t)n * LT + (size_t)j * TC;
    const float2* p = (const float2*)(x + row0 * CC + c0);

    float* obase = out + row0 * OUTW + (size_t)i * 384 + c0;
    float* ibase = out + OUT_ELEMS + (size_t)i * NLC + row0 * CC + c0;
    float* abase = ibase + 3 * NLC;

    const float inv_L = 1.0f / (float)LT;

#pragma unroll 4
    for (int t = 0; t < TC; ++t) {
        const int T = j * TC + t;
        float2 v = p[(size_t)t * (CC / 2)];
        ps0 += v.x; ps1 += v.y;
        if (v.x > pm0) { pm0 = v.x; pa0 = T; }
        if (v.y > pm1) { pm1 = v.y; pa1 = T; }

        const bool pad = (T < LT - 1);        // window still contains left-pad zeros
        const float padi = (float)(T - (LT - 1));
        float2 pmax = make_float2(pad ? fmaxf(pm0, 0.f) : pm0,
                                  pad ? fmaxf(pm1, 0.f) : pm1);
        float2 ind = make_float2((pad && pm0 < 0.f) ? padi : (float)pa0,
                                 (pad && pm1 < 0.f) ? padi : (float)pa1);
        float2 pavg = make_float2(ps0 * inv_L, ps1 * inv_L);
        const float rc = __frcp_rn((float)(T + 1));
        float2 psum = make_float2(ps0 * rc, ps1 * rc);

        float* orow = obase + (size_t)t * OUTW;
        __stcs((float2*)(orow),        pmax);
        __stcs((float2*)(orow + 128),  pavg);
        __stcs((float2*)(orow + 256),  psum);
        __stcs((float2*)(ibase + t * CC), ind);
        __stcs((float2*)(abase + t * CC), pmax);
    }

    // -- demographic broadcast cols [1152:1172): one warp per chunk (i==0) ----
    if (i == 0 && half == 0) {
        float4 dv[5];
#pragma unroll
        for (int g = 0; g < 5; ++g)
            dv[g] = *(const float4*)&d_sh[4 * g];
#pragma unroll
        for (int q = l; q < TC * 5; q += 32) {
            const int t = q / 5, g = q % 5;
            __stcs((float4*)(out + (row0 + t) * OUTW + 1152 + 4 * g), dv[g]);
        }
    }
}

extern "C" void kernel_launch(void* const* d_in, const int* in_sizes, int n_in,
                              void* d_out, int out_size) {
    const float* inp0 = (const float*)d_in[0];
    const float* inp1 = (const float*)d_in[1];
    const float* inp2 = (const float*)d_in[2];
    const float* dem  = (const float*)d_in[3];
    const float* W1   = (const float*)d_in[4];
    const float* b1   = (const float*)d_in[5];
    const float* W2   = (const float*)d_in[6];
    const float* b2   = (const float*)d_in[7];
    float* out = (float*)d_out;

    dim3 agrid(J / 8, NB, 3);    // 8 x 32 x 3 = 768 blocks, warp per chunk
    agg_kernel<<<agrid, 256>>>(inp0, inp1, inp2);
    dim3 egrid(J / 4, NB, 3);    // 16 x 32 x 3 = 1536 blocks, 2 warps per chunk
    emit_kernel<<<egrid, 256>>>(inp0, inp1, inp2, dem, W1, b1, W2, b2, out);
}